// round 2
// baseline (speedup 1.0000x reference)
#include <cuda_runtime.h>

#define NCLS 19
#define NSRC 16384   // 128*128 source pixels
#define NDIM 64

// Scratch (no allocations allowed)
__device__ unsigned char g_count[NCLS * NSRC];   // per-class per-source-pixel multiplicity (0..16)
__device__ float g_partial[NCLS * NDIM];         // per-(class,d) sum over 7 bins of smooth-l1
__device__ float g_ncount[NCLS];                 // per-class pixel count (float)

__device__ __forceinline__ float warp_sum(float v) {
#pragma unroll
    for (int o = 16; o; o >>= 1) v += __shfl_xor_sync(0xffffffffu, v, o);
    return v;
}

// Kernel A: for each source pixel, count labels in its 4x4 upsampled block.
__global__ void __launch_bounds__(256) count_kernel(const int* __restrict__ label) {
    __shared__ unsigned char sc[256 * 20];  // 20-byte stride: conflict-free (gcd(5,32)=1 in words)
    const int tid = threadIdx.x;
#pragma unroll
    for (int c = 0; c < 20; ++c) sc[tid * 20 + c] = 0;
    const int i = blockIdx.x * 256 + tid;       // src index in [0,16384)
    const int sy = i >> 7, sx = i & 127;
    const int4* lab4 = (const int4*)label;      // 512-wide rows, 4sx is 16B aligned
#pragma unroll
    for (int r = 0; r < 4; ++r) {
        int4 v = lab4[(4 * sy + r) * 128 + sx];
        sc[tid * 20 + v.x]++;
        sc[tid * 20 + v.y]++;
        sc[tid * 20 + v.z]++;
        sc[tid * 20 + v.w]++;
    }
#pragma unroll
    for (int c = 0; c < NCLS; ++c)
        g_count[c * NSRC + i] = sc[tid * 20 + c];
}

// Kernel B: one block per (class c, feature dim d).
// Pass 1: weighted mean/var. Pass 2: 7-bin KDE sums. Then per-(c,d) smooth-l1 partial.
__global__ void __launch_bounds__(256) class_kernel(const float* __restrict__ feature) {
    const int d = blockIdx.x;
    const int c = blockIdx.y;
    const int tid = threadIdx.x;
    const int lane = tid & 31, warp = tid >> 5;
    const float* __restrict__ frow = feature + d * NSRC;
    const unsigned char* __restrict__ crow = g_count + c * NSRC;

    // ---- Pass 1: n, sum(w*f), sum(w*f^2) ----
    float s0 = 0.f, s1 = 0.f, s2 = 0.f;
    for (int s = tid; s < NSRC; s += 256) {
        float w = (float)crow[s];
        float f = frow[s];
        s0 += w;
        s1 = fmaf(w, f, s1);
        s2 = fmaf(w * f, f, s2);
    }
    __shared__ float sred[24];
    __shared__ float sstat[3];
    float r0 = warp_sum(s0), r1 = warp_sum(s1), r2 = warp_sum(s2);
    if (lane == 0) { sred[warp] = r0; sred[8 + warp] = r1; sred[16 + warp] = r2; }
    __syncthreads();
    if (tid == 0) {
        float a0 = 0.f, a1 = 0.f, a2 = 0.f;
#pragma unroll
        for (int j = 0; j < 8; ++j) { a0 += sred[j]; a1 += sred[8 + j]; a2 += sred[16 + j]; }
        float n = a0;
        float nsafe = fmaxf(n, 1.0f);
        float miu = a1 / nsafe;
        float var = fmaxf(fmaf(-miu, miu, a2 / nsafe), 0.0f) + 1e-10f;
        sstat[0] = miu;
        sstat[1] = 1.0f / sqrtf(var);
        sstat[2] = n;
    }
    __syncthreads();
    const float miu = sstat[0], istd = sstat[1];

    // ---- Pass 2: KDE sums S_k = sum_src w * exp(-12.5*(k-u)^2), u=(f-miu)/sigma ----
    float bins[7];
#pragma unroll
    for (int k = 0; k < 7; ++k) bins[k] = 0.f;
    for (int s = tid; s < NSRC; s += 256) {
        float w = (float)crow[s];
        float u = (frow[s] - miu) * istd;
#pragma unroll
        for (int k = 0; k < 7; ++k) {
            float t = (float)(k - 3) - u;
            bins[k] = fmaf(w, expf(-12.5f * t * t), bins[k]);
        }
    }
    __shared__ float sb[56];
#pragma unroll
    for (int k = 0; k < 7; ++k) {
        float v = warp_sum(bins[k]);
        if (lane == 0) sb[k * 8 + warp] = v;
    }
    __syncthreads();
    if (tid == 0) {
        float S[7]; float tot = 0.f;
#pragma unroll
        for (int k = 0; k < 7; ++k) {
            float v = 0.f;
#pragma unroll
            for (int j = 0; j < 8; ++j) v += sb[k * 8 + j];
            S[k] = v; tot += v;
        }
        float denom = fmaxf(tot, 1e-30f);
        // target histogram: exp(-0.5 k^2) normalized (identical for all d)
        float tv[7]; float tt = 0.f;
#pragma unroll
        for (int k = 0; k < 7; ++k) {
            float kf = (float)(k - 3);
            tv[k] = expf(-0.5f * kf * kf);
            tt += tv[k];
        }
        float lsum = 0.f;
#pragma unroll
        for (int k = 0; k < 7; ++k) {
            float h = S[k] / denom;
            float t = tv[k] / tt;
            float ad = fabsf(h - t);
            lsum += (ad < 1.0f) ? 0.5f * ad * ad : ad - 0.5f;
        }
        g_partial[c * NDIM + d] = lsum;
        if (d == 0) g_ncount[c] = sstat[2];
    }
}

// Kernel C: deterministic final reduction -> scalar loss.
__global__ void __launch_bounds__(32) finalize_kernel(float* __restrict__ out) {
    const int tid = threadIdx.x;
    __shared__ float cls[NCLS];
    if (tid < NCLS) {
        float s = 0.f;
        for (int dd = 0; dd < NDIM; ++dd) s += g_partial[tid * NDIM + dd];
        cls[tid] = s;
    }
    __syncthreads();
    if (tid == 0) {
        float lsum = 0.f, asum = 0.f;
        for (int c = 0; c < NCLS; ++c) {
            float act = (g_ncount[c] >= 1000.0f) ? 1.0f : 0.0f;
            lsum += act * (cls[c] * (1.0f / 448.0f));  // mean over D*7 elements
            asum += act;
        }
        out[0] = lsum / asum;
    }
}

extern "C" void kernel_launch(void* const* d_in, const int* in_sizes, int n_in,
                              void* d_out, int out_size) {
    // metadata order: feature (1*64*128*128 = 1048576 f32), label (512*512 = 262144 i32).
    const float* feature = (const float*)d_in[0];
    const int*   label   = (const int*)d_in[1];
    if (n_in >= 2 && in_sizes[0] == 262144 && in_sizes[1] == 1048576) {
        // defensive: inputs arrived in the other order
        feature = (const float*)d_in[1];
        label   = (const int*)d_in[0];
    }
    count_kernel<<<64, 256>>>(label);
    class_kernel<<<dim3(NDIM, NCLS), 256>>>(feature);
    finalize_kernel<<<1, 32>>>((float*)d_out);
}

// round 3
// speedup vs baseline: 1.1793x; 1.1793x over previous
#include <cuda_runtime.h>

#define NCLS 19
#define NSRC 16384   // 128*128 source pixels
#define NDIM 64
#define DB   4       // feature dims per block in class_kernel

// exp(-12.5 t^2) = 2^(-(S*t)^2),  S = sqrt(12.5 * log2(e)) = sqrt(18.033688011112043)
#define SCALE_S 4.24660901f

// Scratch (no allocations allowed)
__device__ unsigned char g_count[NCLS * NSRC];   // per-class per-source-pixel multiplicity (0..16)
__device__ unsigned int  g_list[NCLS * NSRC];    // compacted (w<<14)|idx per class, ordered
__device__ int           g_nnz[NCLS];
__device__ float g_partial[NCLS * NDIM];         // per-(class,d) sum over 7 bins of smooth-l1
__device__ float g_ncount[NCLS];                 // per-class pixel count (float)

__device__ __forceinline__ float warp_sum(float v) {
#pragma unroll
    for (int o = 16; o; o >>= 1) v += __shfl_xor_sync(0xffffffffu, v, o);
    return v;
}

__device__ __forceinline__ float ex2(float x) {
    float r;
    asm("ex2.approx.f32 %0, %1;" : "=f"(r) : "f"(x));
    return r;
}

// Kernel A: for each source pixel, count labels in its 4x4 upsampled block.
__global__ void __launch_bounds__(128) count_kernel(const int* __restrict__ label) {
    __shared__ unsigned char sc[128 * 20];  // stride 20 bytes: 5 words, gcd(5,32)=1 -> conflict-free
    const int tid = threadIdx.x;
#pragma unroll
    for (int c = 0; c < 20; ++c) sc[tid * 20 + c] = 0;
    const int i = blockIdx.x * 128 + tid;       // src index in [0,16384)
    const int sy = i >> 7, sx = i & 127;
    const int4* lab4 = (const int4*)label;      // 512-wide rows, 4*sx is 16B aligned
#pragma unroll
    for (int r = 0; r < 4; ++r) {
        int4 v = lab4[(4 * sy + r) * 128 + sx];
        sc[tid * 20 + v.x]++;
        sc[tid * 20 + v.y]++;
        sc[tid * 20 + v.z]++;
        sc[tid * 20 + v.w]++;
    }
#pragma unroll
    for (int c = 0; c < NCLS; ++c)
        g_count[c * NSRC + i] = sc[tid * 20 + c];
}

// Kernel A2: deterministic ordered compaction of nonzero (idx, w) per class.
__global__ void __launch_bounds__(256) compact_kernel() {
    const int c = blockIdx.x;
    const int tid = threadIdx.x, lane = tid & 31, warp = tid >> 5;
    __shared__ int wsum[8];
    __shared__ int sbase;
    if (tid == 0) sbase = 0;
    __syncthreads();
    for (int chunk = 0; chunk < NSRC; chunk += 256) {
        int w = g_count[c * NSRC + chunk + tid];
        unsigned bal = __ballot_sync(0xffffffffu, w > 0);
        int lt = __popc(bal & ((1u << lane) - 1u));
        if (lane == 0) wsum[warp] = __popc(bal);
        __syncthreads();
        int woff = 0, tot = 0;
#pragma unroll
        for (int j = 0; j < 8; ++j) { int v = wsum[j]; if (j < warp) woff += v; tot += v; }
        int base = sbase;
        if (w > 0)
            g_list[c * NSRC + base + woff + lt] = ((unsigned)w << 14) | (unsigned)(chunk + tid);
        __syncthreads();                 // everyone read sbase/wsum
        if (tid == 0) sbase = base + tot;
        __syncthreads();
    }
    if (tid == 0) g_nnz[c] = sbase;
}

// Kernel B: one block per (class c, group of DB feature dims).
// Pass 1: weighted mean/var over compacted list. Pass 2: 7-bin KDE sums via raw ex2.
__global__ void __launch_bounds__(256) class_kernel(const float* __restrict__ feature) {
    const int dg = blockIdx.x;          // 0..NDIM/DB-1
    const int c  = blockIdx.y;
    const int tid = threadIdx.x;
    const int lane = tid & 31, warp = tid >> 5;
    const int d0 = dg * DB;
    const int nnz = g_nnz[c];
    const unsigned int* __restrict__ list = g_list + c * NSRC;
    const float* __restrict__ fbase = feature + d0 * NSRC;

    // ---- Pass 1: n, sum(w*f), sum(w*f^2) per dim ----
    float s0 = 0.f, s1[DB], s2[DB];
#pragma unroll
    for (int j = 0; j < DB; ++j) { s1[j] = 0.f; s2[j] = 0.f; }
    for (int e = tid; e < nnz; e += 256) {
        unsigned v = list[e];
        int idx = (int)(v & 0x3FFFu);
        float w = (float)(v >> 14);
        s0 += w;
#pragma unroll
        for (int j = 0; j < DB; ++j) {
            float f = fbase[j * NSRC + idx];
            s1[j] = fmaf(w, f, s1[j]);
            s2[j] = fmaf(w * f, f, s2[j]);
        }
    }
    __shared__ float sred[(1 + 2 * DB) * 8];
    __shared__ float smiu[DB], sistd[DB], sn;
    {
        float r = warp_sum(s0);
        if (lane == 0) sred[warp] = r;
#pragma unroll
        for (int j = 0; j < DB; ++j) {
            float a = warp_sum(s1[j]);
            float b = warp_sum(s2[j]);
            if (lane == 0) { sred[(1 + 2 * j) * 8 + warp] = a; sred[(2 + 2 * j) * 8 + warp] = b; }
        }
    }
    __syncthreads();
    if (tid == 0) {
        float n = 0.f;
#pragma unroll
        for (int k = 0; k < 8; ++k) n += sred[k];
        float nsafe = fmaxf(n, 1.0f);
        sn = n;
#pragma unroll
        for (int j = 0; j < DB; ++j) {
            float a = 0.f, b = 0.f;
#pragma unroll
            for (int k = 0; k < 8; ++k) { a += sred[(1 + 2 * j) * 8 + k]; b += sred[(2 + 2 * j) * 8 + k]; }
            float miu = a / nsafe;
            float var = fmaxf(fmaf(-miu, miu, b / nsafe), 0.0f) + 1e-10f;
            smiu[j] = miu;
            sistd[j] = SCALE_S / sqrtf(var);   // fold scale S into 1/std
        }
    }
    __syncthreads();
    float miu[DB], istd_s[DB];
#pragma unroll
    for (int j = 0; j < DB; ++j) { miu[j] = smiu[j]; istd_s[j] = sistd[j]; }

    // ---- Pass 2: S_k = sum w * 2^(-(S*(k-u))^2) ----
    float acc[DB][7];
#pragma unroll
    for (int j = 0; j < DB; ++j)
#pragma unroll
        for (int k = 0; k < 7; ++k) acc[j][k] = 0.f;

    for (int e = tid; e < nnz; e += 256) {
        unsigned v = list[e];
        int idx = (int)(v & 0x3FFFu);
        float w = (float)(v >> 14);
#pragma unroll
        for (int j = 0; j < DB; ++j) {
            float su = (fbase[j * NSRC + idx] - miu[j]) * istd_s[j];  // S*u
#pragma unroll
            for (int k = 0; k < 7; ++k) {
                float t = (float)(k - 3) * SCALE_S - su;              // S*(k-u); const folded
                float e2 = ex2(-(t * t));
                acc[j][k] = fmaf(w, e2, acc[j][k]);
            }
        }
    }

    __shared__ float sb[DB * 7 * 8];
#pragma unroll
    for (int j = 0; j < DB; ++j)
#pragma unroll
        for (int k = 0; k < 7; ++k) {
            float v = warp_sum(acc[j][k]);
            if (lane == 0) sb[(j * 7 + k) * 8 + warp] = v;
        }
    __syncthreads();

    if (tid < DB) {
        const int j = tid;
        float S[7]; float tot = 0.f;
#pragma unroll
        for (int k = 0; k < 7; ++k) {
            float v = 0.f;
#pragma unroll
            for (int q = 0; q < 8; ++q) v += sb[(j * 7 + k) * 8 + q];
            S[k] = v; tot += v;
        }
        float denom = fmaxf(tot, 1e-30f);
        // target histogram: exp(-0.5 k^2), normalized (identical for all d)
        float tv[7]; float tt = 0.f;
#pragma unroll
        for (int k = 0; k < 7; ++k) {
            float kf = (float)(k - 3);
            tv[k] = expf(-0.5f * kf * kf);
            tt += tv[k];
        }
        float lsum = 0.f;
#pragma unroll
        for (int k = 0; k < 7; ++k) {
            float h = S[k] / denom;
            float t = tv[k] / tt;
            float ad = fabsf(h - t);
            lsum += (ad < 1.0f) ? 0.5f * ad * ad : ad - 0.5f;
        }
        g_partial[c * NDIM + d0 + j] = lsum;
        if (d0 + j == 0) g_ncount[c] = sn;
    }
}

// Kernel C: deterministic final reduction -> scalar loss.
__global__ void __launch_bounds__(32) finalize_kernel(float* __restrict__ out) {
    const int tid = threadIdx.x;
    __shared__ float cls[NCLS];
    if (tid < NCLS) {
        float s = 0.f;
        for (int dd = 0; dd < NDIM; ++dd) s += g_partial[tid * NDIM + dd];
        cls[tid] = s;
    }
    __syncthreads();
    if (tid == 0) {
        float lsum = 0.f, asum = 0.f;
        for (int c = 0; c < NCLS; ++c) {
            float act = (g_ncount[c] >= 1000.0f) ? 1.0f : 0.0f;
            lsum += act * (cls[c] * (1.0f / (float)(NDIM * 7)));  // mean over D*7 elements
            asum += act;
        }
        out[0] = lsum / asum;
    }
}

extern "C" void kernel_launch(void* const* d_in, const int* in_sizes, int n_in,
                              void* d_out, int out_size) {
    const float* feature = (const float*)d_in[0];
    const int*   label   = (const int*)d_in[1];
    if (n_in >= 2 && in_sizes[0] == 262144 && in_sizes[1] == 1048576) {
        feature = (const float*)d_in[1];
        label   = (const int*)d_in[0];
    }
    count_kernel<<<128, 128>>>(label);
    compact_kernel<<<NCLS, 256>>>();
    class_kernel<<<dim3(NDIM / DB, NCLS), 256>>>(feature);
    finalize_kernel<<<1, 32>>>((float*)d_out);
}